// round 6
// baseline (speedup 1.0000x reference)
#include <cuda_runtime.h>

#define Nn 50000
#define INd 128
#define Hh 4
#define Ff 32
#define Ee 500000
#define Ll 512
#define SLOPE 0.2f

// ---------------- device scratch (static, allocation-free) ----------------
__device__ __align__(16) float    g_fs[Nn * INd];       // feat_src (N,128)
__device__ __align__(16) float    g_fd[Nn * INd];       // feat_dst (N,128)
__device__ __align__(16) float    g_as[2][Ee * Hh];     // unnormalized exp(logit), CSR-sorted
__device__ __align__(16) float    g_segsum[2][Nn * Hh]; // softmax denominators
__device__               int      g_cnt[2][Nn];         // in-degree histogram
__device__               int      g_off[2][Nn + 1];     // CSR offsets
__device__               int      g_cur[2][Nn];         // fill cursors
__device__               int      g_pos[2][Ee];         // edge -> CSR slot
__device__               int      g_srcs[2][Ee];        // src ids, CSR-sorted
__device__               int      g_flag_fmt;           // 0=int32, 1=uint8, 2=float32

// ---------------- flag format detection (single block, deterministic) ----------------
__global__ void k_flagfmt(const unsigned* __restrict__ p) {
    __shared__ int s_word_not01, s_byte_not01;
    if (threadIdx.x == 0) { s_word_not01 = 0; s_byte_not01 = 0; }
    __syncthreads();
    const int nwords = Nn / 4;
    int w_bad = 0, b_bad = 0;
    for (int i = threadIdx.x; i < nwords; i += blockDim.x) {
        unsigned w = p[i];
        if (w > 1u) w_bad = 1;
        unsigned b0 = w & 0xFFu, b1 = (w >> 8) & 0xFFu, b2 = (w >> 16) & 0xFFu, b3 = (w >> 24) & 0xFFu;
        if (b0 > 1u || b1 > 1u || b2 > 1u || b3 > 1u) b_bad = 1;
    }
    if (w_bad) atomicOr(&s_word_not01, 1);
    if (b_bad) atomicOr(&s_byte_not01, 1);
    __syncthreads();
    if (threadIdx.x == 0) {
        int fmt;
        if (!s_word_not01) fmt = 0;
        else if (!s_byte_not01) fmt = 1;
        else fmt = 2;
        g_flag_fmt = fmt;
    }
}

// ---------------- init: zero softmax denoms + histograms ----------------
__global__ void k_init() {
    int tid = blockIdx.x * blockDim.x + threadIdx.x;
    int stride = gridDim.x * blockDim.x;
    float* ss = (float*)g_segsum;
    const int nseg = 2 * Nn * Hh;
    for (int i = tid; i < nseg; i += stride) ss[i] = 0.f;
    int* cnt = (int*)g_cnt;
    for (int i = tid; i < 2 * Nn; i += stride) cnt[i] = 0;
}

// ---------------- projection: fs = x W_src^T + b_src ; fd likewise ----------------
#define BR 16
__global__ void k_proj(const float* __restrict__ x,
                       const float* __restrict__ Ws, const float* __restrict__ bs,
                       const float* __restrict__ Wd, const float* __restrict__ bd) {
    __shared__ float xs[BR][INd];
    const int row0 = blockIdx.x * BR;
    for (int i = threadIdx.x; i < BR * INd; i += blockDim.x) {
        int r = i / INd, c = i % INd;
        xs[r][c] = x[(row0 + r) * INd + c];
    }
    __syncthreads();
    const int col = threadIdx.x;
    float accS[BR], accD[BR];
#pragma unroll
    for (int r = 0; r < BR; r++) { accS[r] = 0.f; accD[r] = 0.f; }
    const float* wsr = Ws + col * INd;
    const float* wdr = Wd + col * INd;
    for (int k = 0; k < INd; k++) {
        float ws = __ldg(wsr + k);
        float wd = __ldg(wdr + k);
#pragma unroll
        for (int r = 0; r < BR; r++) {
            float xv = xs[r][k];
            accS[r] += xv * ws;
            accD[r] += xv * wd;
        }
    }
    float bsv = bs[col], bdv = bd[col];
#pragma unroll
    for (int r = 0; r < BR; r++) {
        g_fs[(row0 + r) * INd + col] = accS[r] + bsv;
        g_fd[(row0 + r) * INd + col] = accD[r] + bdv;
    }
}

// ---------------- CSR build: histogram -> scan -> fill (both graphs fused) ----------------
__global__ void k_hist(const int* __restrict__ dst_p, const int* __restrict__ dst_s, int et) {
    const int g = blockIdx.x >= et;
    const int e = (blockIdx.x - g * et) * blockDim.x + threadIdx.x;
    if (e < Ee) atomicAdd(&g_cnt[g][(g ? dst_s : dst_p)[e]], 1);
}

__global__ void k_scan() {  // grid = 2 (one block per graph), 1024 threads
    const int g = blockIdx.x;
    const int t = threadIdx.x;
    const int lane = t & 31, w = t >> 5;
    __shared__ int wsum[32];
    __shared__ int s_carry;
    if (t == 0) { g_off[g][0] = 0; s_carry = 0; }
    __syncthreads();
    for (int base = 0; base < Nn; base += 1024) {
        int i = base + t;
        int c0 = (i < Nn) ? g_cnt[g][i] : 0;
        int v = c0;
#pragma unroll
        for (int o = 1; o < 32; o <<= 1) {
            int u = __shfl_up_sync(0xFFFFFFFFu, v, o);
            if (lane >= o) v += u;
        }
        if (lane == 31) wsum[w] = v;
        __syncthreads();
        if (w == 0) {
            int sv = wsum[lane];
#pragma unroll
            for (int o = 1; o < 32; o <<= 1) {
                int u = __shfl_up_sync(0xFFFFFFFFu, sv, o);
                if (lane >= o) sv += u;
            }
            wsum[lane] = sv;
        }
        __syncthreads();
        int add = (w > 0) ? wsum[w - 1] : 0;
        int incl = v + add + s_carry;
        if (i < Nn) {
            g_off[g][i + 1] = incl;
            g_cur[g][i] = incl - c0;
        }
        __syncthreads();
        if (t == 1023) s_carry = incl;
        __syncthreads();
    }
}

__global__ void k_fill(const int* __restrict__ src_p, const int* __restrict__ dst_p,
                       const int* __restrict__ src_s, const int* __restrict__ dst_s, int et) {
    const int g = blockIdx.x >= et;
    const int e = (blockIdx.x - g * et) * blockDim.x + threadIdx.x;
    if (e >= Ee) return;
    const int d = (g ? dst_s : dst_p)[e];
    const int s = (g ? src_s : src_p)[e];
    int pos = atomicAdd(&g_cur[g][d], 1);
    g_pos[g][e] = pos;
    g_srcs[g][pos] = s;
}

// ---------------- logits + exp + segment sum (warp per edge, both graphs) ----------------
__global__ void k_logexp(const int* __restrict__ src_p, const int* __restrict__ dst_p,
                         const int* __restrict__ src_s, const int* __restrict__ dst_s,
                         const float* __restrict__ attn, int ew) {
    const int g = blockIdx.x >= ew;
    const int warp = threadIdx.x >> 5;
    const int lane = threadIdx.x & 31;
    const int e = (blockIdx.x - g * ew) * (blockDim.x >> 5) + warp;
    if (e >= Ee) return;
    const int s = (g ? src_s : src_p)[e];
    const int d = (g ? dst_s : dst_p)[e];
    const float4 fs4 = __ldg(((const float4*)g_fs) + s * 32 + lane);
    const float4 fd4 = __ldg(((const float4*)g_fd) + d * 32 + lane);
    const float4 at  = __ldg(((const float4*)attn) + lane);
    float v, p;
    v = fs4.x + fd4.x; v = v > 0.f ? v : SLOPE * v; p  = v * at.x;
    v = fs4.y + fd4.y; v = v > 0.f ? v : SLOPE * v; p += v * at.y;
    v = fs4.z + fd4.z; v = v > 0.f ? v : SLOPE * v; p += v * at.z;
    v = fs4.w + fd4.w; v = v > 0.f ? v : SLOPE * v; p += v * at.w;
    // reduce within each 8-lane group (one head per group)
    p += __shfl_xor_sync(0xFFFFFFFFu, p, 4);
    p += __shfl_xor_sync(0xFFFFFFFFu, p, 2);
    p += __shfl_xor_sync(0xFFFFFFFFu, p, 1);
    const float h0 = __shfl_sync(0xFFFFFFFFu, p, 0);
    const float h1 = __shfl_sync(0xFFFFFFFFu, p, 8);
    const float h2 = __shfl_sync(0xFFFFFFFFu, p, 16);
    const float h3 = __shfl_sync(0xFFFFFFFFu, p, 24);
    if (lane == 0) {
        const int pos = g_pos[g][e];
        float4 ex;
        ex.x = expf(h0); ex.y = expf(h1); ex.z = expf(h2); ex.w = expf(h3);
        ((float4*)g_as[g])[pos] = ex;
    }
    if ((lane & 7) == 0) {
        atomicAdd(&g_segsum[g][d * Hh + (lane >> 3)], expf(p));
    }
}

// ---------------- fused gather: 4 partition-warps per node, smem combine ----------------
__global__ void __launch_bounds__(256) k_gather(
        const float* __restrict__ x, const float* __restrict__ y,
        const void* __restrict__ flag, float* __restrict__ out) {
    const int warp = threadIdx.x >> 5;
    const int lane = threadIdx.x & 31;
    const int sub = warp & 3;                 // partition index within node
    const int nb = warp >> 2;                 // node-in-block (0/1)
    const int n = blockIdx.x * 2 + nb;

    __shared__ float4 s_yh[2][4][128];        // 16 KB
    __shared__ float4 s_acc[2][4][32];        // 4 KB
    __shared__ float  s_ssq[2][4];

    // per-node softmax denominators -> reciprocals (per graph, per head)
    const float4 sum0 = __ldg(((const float4*)g_segsum[0]) + n);
    const float4 sum1 = __ldg(((const float4*)g_segsum[1]) + n);
    float4 r0, r1;
    r0.x = 1.f / sum0.x; r0.y = 1.f / sum0.y; r0.z = 1.f / sum0.z; r0.w = 1.f / sum0.w;
    r1.x = 1.f / sum1.x; r1.y = 1.f / sum1.y; r1.z = 1.f / sum1.z; r1.w = 1.f / sum1.w;

    float4 acc = make_float4(0.f, 0.f, 0.f, 0.f);   // partial feature acc (128 floats/warp)
    float4 yh[4];                                    // partial label acc (512 floats/warp)
#pragma unroll
    for (int i = 0; i < 4; i++) yh[i] = make_float4(0.f, 0.f, 0.f, 0.f);

    const float4* __restrict__ y4 = (const float4*)y;
    const float4* __restrict__ fs4 = (const float4*)g_fs;

#pragma unroll
    for (int g = 0; g < 2; g++) {
        const float4 rs = g ? r1 : r0;
        const int beg = g_off[g][n];
        const int end = g_off[g][n + 1];
        const int* __restrict__ ps = g_srcs[g];
        const float4* __restrict__ pa = (const float4*)g_as[g];
        for (int k = beg + sub; k < end; k += 4) {
            const int s = __ldg(ps + k);
            float4 a4 = __ldg(pa + k);
            a4.x *= rs.x; a4.y *= rs.y; a4.z *= rs.z; a4.w *= rs.w;
            const float am = 0.25f * (a4.x + a4.y + a4.z + a4.w);
            const float ah = (lane < 8) ? a4.x : (lane < 16) ? a4.y : (lane < 24) ? a4.z : a4.w;
            const float4 fv = __ldg(fs4 + s * 32 + lane);
            acc.x += fv.x * ah; acc.y += fv.y * ah;
            acc.z += fv.z * ah; acc.w += fv.w * ah;
            const float4* py = y4 + (size_t)s * 128;
#pragma unroll
            for (int i = 0; i < 4; i++) {
                const float4 v = __ldg(py + i * 32 + lane);
                yh[i].x += v.x * am; yh[i].y += v.y * am;
                yh[i].z += v.z * am; yh[i].w += v.w * am;
            }
        }
    }

    // stash partials
    s_acc[nb][sub][lane] = acc;
#pragma unroll
    for (int i = 0; i < 4; i++) s_yh[nb][sub][i * 32 + lane] = yh[i];
    __syncthreads();

    // ---- epilogue h: warp sub==0 of each node combines 4 partials + residual
    if (sub == 0) {
        float4 a0 = s_acc[nb][0][lane], a1 = s_acc[nb][1][lane];
        float4 a2 = s_acc[nb][2][lane], a3 = s_acc[nb][3][lane];
        const float4 xr = __ldg(((const float4*)x) + n * 32 + lane);
        float4 a;
        a.x = a0.x + a1.x + a2.x + a3.x + 2.f * xr.x;
        a.y = a0.y + a1.y + a2.y + a3.y + 2.f * xr.y;
        a.z = a0.z + a1.z + a2.z + a3.z + 2.f * xr.z;
        a.w = a0.w + a1.w + a2.w + a3.w + 2.f * xr.w;
#pragma unroll
        for (int o = 8; o <= 16; o <<= 1) {
            a.x += __shfl_xor_sync(0xFFFFFFFFu, a.x, o);
            a.y += __shfl_xor_sync(0xFFFFFFFFu, a.y, o);
            a.z += __shfl_xor_sync(0xFFFFFFFFu, a.z, o);
            a.w += __shfl_xor_sync(0xFFFFFFFFu, a.w, o);
        }
        if (lane < 8) {
            float4 r;
            r.x = a.x * 0.25f; r.y = a.y * 0.25f; r.z = a.z * 0.25f; r.w = a.w * 0.25f;
            r.x = r.x > 0.f ? r.x : expm1f(r.x);
            r.y = r.y > 0.f ? r.y : expm1f(r.y);
            r.z = r.z > 0.f ? r.z : expm1f(r.z);
            r.w = r.w > 0.f ? r.w : expm1f(r.w);
            ((float4*)out)[n * 8 + lane] = r;
        }
    }

    // ---- epilogue y: each warp combines + writes one 128-float chunk (j = sub*32+lane)
    const int j = sub * 32 + lane;
    float4 t0 = s_yh[nb][0][j], t1 = s_yh[nb][1][j];
    float4 t2 = s_yh[nb][2][j], t3 = s_yh[nb][3][j];
    float4 t;
    t.x = t0.x + t1.x + t2.x + t3.x;
    t.y = t0.y + t1.y + t2.y + t3.y;
    t.z = t0.z + t1.z + t2.z + t3.z;
    t.w = t0.w + t1.w + t2.w + t3.w;
    float ssq = t.x * t.x + t.y * t.y + t.z * t.z + t.w * t.w;
#pragma unroll
    for (int o = 16; o; o >>= 1) ssq += __shfl_xor_sync(0xFFFFFFFFu, ssq, o);
    if (lane == 0) s_ssq[nb][sub] = ssq;
    __syncthreads();
    const float tot = s_ssq[nb][0] + s_ssq[nb][1] + s_ssq[nb][2] + s_ssq[nb][3];
    const float inv = 1.f / fmaxf(sqrtf(tot), 1e-12f);

    bool f;
    const int fmt = g_flag_fmt;
    if (fmt == 0)      f = ((const int*)flag)[n] != 0;
    else if (fmt == 1) f = ((const unsigned char*)flag)[n] != 0;
    else               f = ((const float*)flag)[n] != 0.f;

    float4* po = (float4*)(out + (size_t)Nn * Ff) + (size_t)n * 128 + j;
    if (f) {
        *po = __ldg(y4 + (size_t)n * 128 + j);
    } else {
        float4 w = t;
        w.x *= inv; w.y *= inv; w.z *= inv; w.w *= inv;
        *po = w;
    }
}

// ---------------- launch ----------------
extern "C" void kernel_launch(void* const* d_in, const int* in_sizes, int n_in,
                              void* d_out, int out_size) {
    const float* x     = (const float*)d_in[0];
    const float* y     = (const float*)d_in[1];
    const float* Ws    = (const float*)d_in[2];
    const float* bs    = (const float*)d_in[3];
    const float* Wd    = (const float*)d_in[4];
    const float* bd    = (const float*)d_in[5];
    const float* attn  = (const float*)d_in[6];
    const int*   src_p = (const int*)d_in[7];
    const int*   dst_p = (const int*)d_in[8];
    const int*   src_s = (const int*)d_in[9];
    const int*   dst_s = (const int*)d_in[10];
    const void*  dflag = d_in[11];
    float* out = (float*)d_out;

    const int et = (Ee + 255) / 256;   // thread-per-edge blocks (per graph)
    const int ew = (Ee + 7) / 8;       // warp-per-edge blocks (per graph)

    k_flagfmt<<<1, 256>>>((const unsigned*)dflag);
    k_init<<<128, 256>>>();
    k_proj<<<Nn / BR, 128>>>(x, Ws, bs, Wd, bd);

    k_hist<<<2 * et, 256>>>(dst_p, dst_s, et);
    k_scan<<<2, 1024>>>();
    k_fill<<<2 * et, 256>>>(src_p, dst_p, src_s, dst_s, et);

    k_logexp<<<2 * ew, 256>>>(src_p, dst_p, src_s, dst_s, attn, ew);

    k_gather<<<Nn / 2, 256>>>(x, y, dflag, out);
}

// round 7
// speedup vs baseline: 1.0224x; 1.0224x over previous
#include <cuda_runtime.h>

#define Nn 50000
#define INd 128
#define Hh 4
#define Ff 32
#define Ee 500000
#define Ll 512
#define SLOPE 0.2f

// ---------------- device scratch (static, allocation-free) ----------------
__device__ __align__(16) float    g_fs[Nn * INd];       // feat_src (N,128)
__device__ __align__(16) float    g_fd[Nn * INd];       // feat_dst (N,128)
__device__ __align__(16) float    g_as[2][Ee * Hh];     // unnormalized exp(logit), CSR-sorted
__device__ __align__(16) float    g_segsum[2][Nn * Hh]; // softmax denominators
__device__               int      g_cnt[2][Nn];         // in-degree histogram
__device__               int      g_off[2][Nn + 1];     // CSR offsets
__device__               int      g_cur[2][Nn];         // fill cursors
__device__               int      g_pos[2][Ee];         // edge -> CSR slot
__device__               int      g_srcs[2][Ee];        // src ids, CSR-sorted
__device__               int      g_flag_fmt;           // 0=int32, 1=uint8, 2=float32

// ---------------- flag format detection (single block, deterministic) ----------------
__global__ void k_flagfmt(const unsigned* __restrict__ p) {
    __shared__ int s_word_not01, s_byte_not01;
    if (threadIdx.x == 0) { s_word_not01 = 0; s_byte_not01 = 0; }
    __syncthreads();
    const int nwords = Nn / 4;
    int w_bad = 0, b_bad = 0;
    for (int i = threadIdx.x; i < nwords; i += blockDim.x) {
        unsigned w = p[i];
        if (w > 1u) w_bad = 1;
        unsigned b0 = w & 0xFFu, b1 = (w >> 8) & 0xFFu, b2 = (w >> 16) & 0xFFu, b3 = (w >> 24) & 0xFFu;
        if (b0 > 1u || b1 > 1u || b2 > 1u || b3 > 1u) b_bad = 1;
    }
    if (w_bad) atomicOr(&s_word_not01, 1);
    if (b_bad) atomicOr(&s_byte_not01, 1);
    __syncthreads();
    if (threadIdx.x == 0) {
        int fmt;
        if (!s_word_not01) fmt = 0;
        else if (!s_byte_not01) fmt = 1;
        else fmt = 2;
        g_flag_fmt = fmt;
    }
}

// ---------------- init: zero softmax denoms + histograms ----------------
__global__ void k_init() {
    int tid = blockIdx.x * blockDim.x + threadIdx.x;
    int stride = gridDim.x * blockDim.x;
    float* ss = (float*)g_segsum;
    const int nseg = 2 * Nn * Hh;
    for (int i = tid; i < nseg; i += stride) ss[i] = 0.f;
    int* cnt = (int*)g_cnt;
    for (int i = tid; i < 2 * Nn; i += stride) cnt[i] = 0;
}

// ---------------- projection: fs = x W_src^T + b_src ; fd likewise ----------------
#define BR 16
__global__ void k_proj(const float* __restrict__ x,
                       const float* __restrict__ Ws, const float* __restrict__ bs,
                       const float* __restrict__ Wd, const float* __restrict__ bd) {
    __shared__ float xs[BR][INd];
    const int row0 = blockIdx.x * BR;
    for (int i = threadIdx.x; i < BR * INd; i += blockDim.x) {
        int r = i / INd, c = i % INd;
        xs[r][c] = x[(row0 + r) * INd + c];
    }
    __syncthreads();
    const int col = threadIdx.x;
    float accS[BR], accD[BR];
#pragma unroll
    for (int r = 0; r < BR; r++) { accS[r] = 0.f; accD[r] = 0.f; }
    const float* wsr = Ws + col * INd;
    const float* wdr = Wd + col * INd;
    for (int k = 0; k < INd; k++) {
        float ws = __ldg(wsr + k);
        float wd = __ldg(wdr + k);
#pragma unroll
        for (int r = 0; r < BR; r++) {
            float xv = xs[r][k];
            accS[r] += xv * ws;
            accD[r] += xv * wd;
        }
    }
    float bsv = bs[col], bdv = bd[col];
#pragma unroll
    for (int r = 0; r < BR; r++) {
        g_fs[(row0 + r) * INd + col] = accS[r] + bsv;
        g_fd[(row0 + r) * INd + col] = accD[r] + bdv;
    }
}

// ---------------- CSR build: histogram -> scan -> fill (both graphs fused) ----------------
__global__ void k_hist(const int* __restrict__ dst_p, const int* __restrict__ dst_s, int et) {
    const int g = blockIdx.x >= et;
    const int e = (blockIdx.x - g * et) * blockDim.x + threadIdx.x;
    if (e < Ee) atomicAdd(&g_cnt[g][(g ? dst_s : dst_p)[e]], 1);
}

__global__ void k_scan() {  // grid = 2 (one block per graph), 1024 threads
    const int g = blockIdx.x;
    const int t = threadIdx.x;
    const int lane = t & 31, w = t >> 5;
    __shared__ int wsum[32];
    __shared__ int s_carry;
    if (t == 0) { g_off[g][0] = 0; s_carry = 0; }
    __syncthreads();
    for (int base = 0; base < Nn; base += 1024) {
        int i = base + t;
        int c0 = (i < Nn) ? g_cnt[g][i] : 0;
        int v = c0;
#pragma unroll
        for (int o = 1; o < 32; o <<= 1) {
            int u = __shfl_up_sync(0xFFFFFFFFu, v, o);
            if (lane >= o) v += u;
        }
        if (lane == 31) wsum[w] = v;
        __syncthreads();
        if (w == 0) {
            int sv = wsum[lane];
#pragma unroll
            for (int o = 1; o < 32; o <<= 1) {
                int u = __shfl_up_sync(0xFFFFFFFFu, sv, o);
                if (lane >= o) sv += u;
            }
            wsum[lane] = sv;
        }
        __syncthreads();
        int add = (w > 0) ? wsum[w - 1] : 0;
        int incl = v + add + s_carry;
        if (i < Nn) {
            g_off[g][i + 1] = incl;
            g_cur[g][i] = incl - c0;
        }
        __syncthreads();
        if (t == 1023) s_carry = incl;
        __syncthreads();
    }
}

__global__ void k_fill(const int* __restrict__ src_p, const int* __restrict__ dst_p,
                       const int* __restrict__ src_s, const int* __restrict__ dst_s, int et) {
    const int g = blockIdx.x >= et;
    const int e = (blockIdx.x - g * et) * blockDim.x + threadIdx.x;
    if (e >= Ee) return;
    const int d = (g ? dst_s : dst_p)[e];
    const int s = (g ? src_s : src_p)[e];
    int pos = atomicAdd(&g_cur[g][d], 1);
    g_pos[g][e] = pos;
    g_srcs[g][pos] = s;
}

// ---------------- logits + exp + segment sum (warp per edge, both graphs) ----------------
__global__ void k_logexp(const int* __restrict__ src_p, const int* __restrict__ dst_p,
                         const int* __restrict__ src_s, const int* __restrict__ dst_s,
                         const float* __restrict__ attn, int ew) {
    const int g = blockIdx.x >= ew;
    const int warp = threadIdx.x >> 5;
    const int lane = threadIdx.x & 31;
    const int e = (blockIdx.x - g * ew) * (blockDim.x >> 5) + warp;
    if (e >= Ee) return;
    const int s = (g ? src_s : src_p)[e];
    const int d = (g ? dst_s : dst_p)[e];
    const float4 fs4 = __ldg(((const float4*)g_fs) + s * 32 + lane);
    const float4 fd4 = __ldg(((const float4*)g_fd) + d * 32 + lane);
    const float4 at  = __ldg(((const float4*)attn) + lane);
    float v, p;
    v = fs4.x + fd4.x; v = v > 0.f ? v : SLOPE * v; p  = v * at.x;
    v = fs4.y + fd4.y; v = v > 0.f ? v : SLOPE * v; p += v * at.y;
    v = fs4.z + fd4.z; v = v > 0.f ? v : SLOPE * v; p += v * at.z;
    v = fs4.w + fd4.w; v = v > 0.f ? v : SLOPE * v; p += v * at.w;
    // reduce within each 8-lane group (one head per group)
    p += __shfl_xor_sync(0xFFFFFFFFu, p, 4);
    p += __shfl_xor_sync(0xFFFFFFFFu, p, 2);
    p += __shfl_xor_sync(0xFFFFFFFFu, p, 1);
    const float h0 = __shfl_sync(0xFFFFFFFFu, p, 0);
    const float h1 = __shfl_sync(0xFFFFFFFFu, p, 8);
    const float h2 = __shfl_sync(0xFFFFFFFFu, p, 16);
    const float h3 = __shfl_sync(0xFFFFFFFFu, p, 24);
    if (lane == 0) {
        const int pos = g_pos[g][e];
        float4 ex;
        ex.x = expf(h0); ex.y = expf(h1); ex.z = expf(h2); ex.w = expf(h3);
        ((float4*)g_as[g])[pos] = ex;
    }
    if ((lane & 7) == 0) {
        atomicAdd(&g_segsum[g][d * Hh + (lane >> 3)], expf(p));
    }
}

// ---------------- feature gather: warp per node, fs aggregation + h epilogue ----------------
__global__ void __launch_bounds__(256) k_gath_feat(
        const float* __restrict__ x, float* __restrict__ out) {
    const int warp = threadIdx.x >> 5;
    const int lane = threadIdx.x & 31;
    const int n = blockIdx.x * (blockDim.x >> 5) + warp;
    if (n >= Nn) return;

    const float4 sum0 = __ldg(((const float4*)g_segsum[0]) + n);
    const float4 sum1 = __ldg(((const float4*)g_segsum[1]) + n);
    float4 r0, r1;
    r0.x = 1.f / sum0.x; r0.y = 1.f / sum0.y; r0.z = 1.f / sum0.z; r0.w = 1.f / sum0.w;
    r1.x = 1.f / sum1.x; r1.y = 1.f / sum1.y; r1.z = 1.f / sum1.z; r1.w = 1.f / sum1.w;

    float4 acc = __ldg(((const float4*)x) + n * 32 + lane);
    acc.x *= 2.f; acc.y *= 2.f; acc.z *= 2.f; acc.w *= 2.f;

    const float4* __restrict__ fs4 = (const float4*)g_fs;

#pragma unroll
    for (int g = 0; g < 2; g++) {
        const float4 rs = g ? r1 : r0;
        const int beg = g_off[g][n];
        const int end = g_off[g][n + 1];
        const int* __restrict__ ps = g_srcs[g];
        const float4* __restrict__ pa = (const float4*)g_as[g];
        int k = beg;
        for (; k + 1 < end; k += 2) {
            const int s0 = __ldg(ps + k);
            const int s1 = __ldg(ps + k + 1);
            float4 a0 = __ldg(pa + k);
            float4 a1 = __ldg(pa + k + 1);
            const float ah0 = ((lane < 8) ? a0.x : (lane < 16) ? a0.y : (lane < 24) ? a0.z : a0.w)
                            * ((lane < 8) ? rs.x : (lane < 16) ? rs.y : (lane < 24) ? rs.z : rs.w);
            const float ah1 = ((lane < 8) ? a1.x : (lane < 16) ? a1.y : (lane < 24) ? a1.z : a1.w)
                            * ((lane < 8) ? rs.x : (lane < 16) ? rs.y : (lane < 24) ? rs.z : rs.w);
            const float4 f0 = __ldg(fs4 + s0 * 32 + lane);
            const float4 f1 = __ldg(fs4 + s1 * 32 + lane);
            acc.x += f0.x * ah0 + f1.x * ah1;
            acc.y += f0.y * ah0 + f1.y * ah1;
            acc.z += f0.z * ah0 + f1.z * ah1;
            acc.w += f0.w * ah0 + f1.w * ah1;
        }
        if (k < end) {
            const int s0 = __ldg(ps + k);
            float4 a0 = __ldg(pa + k);
            const float ah0 = ((lane < 8) ? a0.x : (lane < 16) ? a0.y : (lane < 24) ? a0.z : a0.w)
                            * ((lane < 8) ? rs.x : (lane < 16) ? rs.y : (lane < 24) ? rs.z : rs.w);
            const float4 f0 = __ldg(fs4 + s0 * 32 + lane);
            acc.x += f0.x * ah0; acc.y += f0.y * ah0;
            acc.z += f0.z * ah0; acc.w += f0.w * ah0;
        }
    }

    // mean over heads + elu; heads of float f live in lanes {f/4, +8, +16, +24}
#pragma unroll
    for (int o = 8; o <= 16; o <<= 1) {
        acc.x += __shfl_xor_sync(0xFFFFFFFFu, acc.x, o);
        acc.y += __shfl_xor_sync(0xFFFFFFFFu, acc.y, o);
        acc.z += __shfl_xor_sync(0xFFFFFFFFu, acc.z, o);
        acc.w += __shfl_xor_sync(0xFFFFFFFFu, acc.w, o);
    }
    if (lane < 8) {
        float4 r;
        r.x = acc.x * 0.25f; r.y = acc.y * 0.25f; r.z = acc.z * 0.25f; r.w = acc.w * 0.25f;
        r.x = r.x > 0.f ? r.x : expm1f(r.x);
        r.y = r.y > 0.f ? r.y : expm1f(r.y);
        r.z = r.z > 0.f ? r.z : expm1f(r.z);
        r.w = r.w > 0.f ? r.w : expm1f(r.w);
        ((float4*)out)[n * 8 + lane] = r;
    }
}

// ---------------- label gather: warp per node; y L2-resident, metadata/out streamed ----------------
__global__ void __launch_bounds__(256) k_gath_label(
        const float* __restrict__ y, const void* __restrict__ flag,
        float* __restrict__ out) {
    const int warp = threadIdx.x >> 5;
    const int lane = threadIdx.x & 31;
    const int n = blockIdx.x * (blockDim.x >> 5) + warp;
    if (n >= Nn) return;

    const float4 sum0 = __ldg(((const float4*)g_segsum[0]) + n);
    const float4 sum1 = __ldg(((const float4*)g_segsum[1]) + n);
    float4 r0, r1;
    r0.x = 0.25f / sum0.x; r0.y = 0.25f / sum0.y; r0.z = 0.25f / sum0.z; r0.w = 0.25f / sum0.w;
    r1.x = 0.25f / sum1.x; r1.y = 0.25f / sum1.y; r1.z = 0.25f / sum1.z; r1.w = 0.25f / sum1.w;

    float4 yh[4];
#pragma unroll
    for (int i = 0; i < 4; i++) yh[i] = make_float4(0.f, 0.f, 0.f, 0.f);

    const float4* __restrict__ y4 = (const float4*)y;

#pragma unroll
    for (int g = 0; g < 2; g++) {
        const float4 rs = g ? r1 : r0;
        const int beg = g_off[g][n];
        const int end = g_off[g][n + 1];
        const int* __restrict__ ps = g_srcs[g];
        const float4* __restrict__ pa = (const float4*)g_as[g];
        int k = beg;
        for (; k + 1 < end; k += 2) {
            const int s0 = __ldcs(ps + k);       // evict-first: read-once streams
            const int s1 = __ldcs(ps + k + 1);
            const float4 a0 = __ldcs(pa + k);
            const float4 a1 = __ldcs(pa + k + 1);
            const float am0 = a0.x * rs.x + a0.y * rs.y + a0.z * rs.z + a0.w * rs.w;
            const float am1 = a1.x * rs.x + a1.y * rs.y + a1.z * rs.z + a1.w * rs.w;
            const float4* py0 = y4 + (size_t)s0 * 128;
            const float4* py1 = y4 + (size_t)s1 * 128;
#pragma unroll
            for (int i = 0; i < 4; i++) {
                const float4 v0 = __ldg(py0 + i * 32 + lane);   // keep y cached
                const float4 v1 = __ldg(py1 + i * 32 + lane);
                yh[i].x += v0.x * am0 + v1.x * am1;
                yh[i].y += v0.y * am0 + v1.y * am1;
                yh[i].z += v0.z * am0 + v1.z * am1;
                yh[i].w += v0.w * am0 + v1.w * am1;
            }
        }
        if (k < end) {
            const int s0 = __ldcs(ps + k);
            const float4 a0 = __ldcs(pa + k);
            const float am0 = a0.x * rs.x + a0.y * rs.y + a0.z * rs.z + a0.w * rs.w;
            const float4* py0 = y4 + (size_t)s0 * 128;
#pragma unroll
            for (int i = 0; i < 4; i++) {
                const float4 v0 = __ldg(py0 + i * 32 + lane);
                yh[i].x += v0.x * am0; yh[i].y += v0.y * am0;
                yh[i].z += v0.z * am0; yh[i].w += v0.w * am0;
            }
        }
    }

    // L2 normalize or passthrough per flag
    float ssq = 0.f;
#pragma unroll
    for (int i = 0; i < 4; i++)
        ssq += yh[i].x * yh[i].x + yh[i].y * yh[i].y + yh[i].z * yh[i].z + yh[i].w * yh[i].w;
#pragma unroll
    for (int o = 16; o; o >>= 1) ssq += __shfl_xor_sync(0xFFFFFFFFu, ssq, o);
    const float inv = 1.f / fmaxf(sqrtf(ssq), 1e-12f);

    bool f;
    const int fmt = g_flag_fmt;
    if (fmt == 0)      f = ((const int*)flag)[n] != 0;
    else if (fmt == 1) f = ((const unsigned char*)flag)[n] != 0;
    else               f = ((const float*)flag)[n] != 0.f;

    float4* po = (float4*)(out + (size_t)Nn * Ff) + (size_t)n * 128;
    if (f) {
        const float4* py = y4 + (size_t)n * 128;
#pragma unroll
        for (int i = 0; i < 4; i++) __stcs(po + i * 32 + lane, __ldg(py + i * 32 + lane));
    } else {
#pragma unroll
        for (int i = 0; i < 4; i++) {
            float4 w = yh[i];
            w.x *= inv; w.y *= inv; w.z *= inv; w.w *= inv;
            __stcs(po + i * 32 + lane, w);      // streaming store: don't pollute L2
        }
    }
}

// ---------------- launch ----------------
extern "C" void kernel_launch(void* const* d_in, const int* in_sizes, int n_in,
                              void* d_out, int out_size) {
    const float* x     = (const float*)d_in[0];
    const float* y     = (const float*)d_in[1];
    const float* Ws    = (const float*)d_in[2];
    const float* bs    = (const float*)d_in[3];
    const float* Wd    = (const float*)d_in[4];
    const float* bd    = (const float*)d_in[5];
    const float* attn  = (const float*)d_in[6];
    const int*   src_p = (const int*)d_in[7];
    const int*   dst_p = (const int*)d_in[8];
    const int*   src_s = (const int*)d_in[9];
    const int*   dst_s = (const int*)d_in[10];
    const void*  dflag = d_in[11];
    float* out = (float*)d_out;

    const int et = (Ee + 255) / 256;   // thread-per-edge blocks (per graph)
    const int ew = (Ee + 7) / 8;       // warp-per-edge blocks (per graph)

    k_flagfmt<<<1, 256>>>((const unsigned*)dflag);
    k_init<<<128, 256>>>();
    k_proj<<<Nn / BR, 128>>>(x, Ws, bs, Wd, bd);

    k_hist<<<2 * et, 256>>>(dst_p, dst_s, et);
    k_scan<<<2, 1024>>>();
    k_fill<<<2 * et, 256>>>(src_p, dst_p, src_s, dst_s, et);

    k_logexp<<<2 * ew, 256>>>(src_p, dst_p, src_s, dst_s, attn, ew);

    k_gath_feat<<<(Nn + 7) / 8, 256>>>(x, out);
    k_gath_label<<<(Nn + 7) / 8, 256>>>(y, dflag, out);
}

// round 8
// speedup vs baseline: 1.1985x; 1.1722x over previous
#include <cuda_runtime.h>

#define Nn 50000
#define INd 128
#define Hh 4
#define Ff 32
#define Ee 500000
#define Ll 512
#define SLOPE 0.2f
#define MAXD 128   // per-warp smem edge stash; P(deg>=128 | Poisson(10)) ~ 1e-80

// ---------------- device scratch (static, allocation-free) ----------------
__device__ __align__(16) float    g_fs[Nn * INd];       // feat_src (N,128)
__device__ __align__(16) float    g_fd[Nn * INd];       // feat_dst (N,128)
__device__               int      g_cnt[2][Nn];         // in-degree histogram
__device__               int      g_off[2][Nn + 1];     // CSR offsets
__device__               int      g_cur[2][Nn];         // fill cursors
__device__               int      g_srcs[2][Ee];        // src ids, CSR-sorted
__device__               int      g_flag_fmt;           // 0=int32, 1=uint8, 2=float32

// ---------------- init: flag detect (block 0) + zero histograms ----------------
__global__ void k_init(const unsigned* __restrict__ p) {
    if (blockIdx.x == 0) {
        __shared__ int s_word_not01, s_byte_not01;
        if (threadIdx.x == 0) { s_word_not01 = 0; s_byte_not01 = 0; }
        __syncthreads();
        const int nwords = Nn / 4;
        int w_bad = 0, b_bad = 0;
        for (int i = threadIdx.x; i < nwords; i += blockDim.x) {
            unsigned w = p[i];
            if (w > 1u) w_bad = 1;
            unsigned b0 = w & 0xFFu, b1 = (w >> 8) & 0xFFu, b2 = (w >> 16) & 0xFFu, b3 = (w >> 24) & 0xFFu;
            if (b0 > 1u || b1 > 1u || b2 > 1u || b3 > 1u) b_bad = 1;
        }
        if (w_bad) atomicOr(&s_word_not01, 1);
        if (b_bad) atomicOr(&s_byte_not01, 1);
        __syncthreads();
        if (threadIdx.x == 0) {
            int fmt;
            if (!s_word_not01) fmt = 0;
            else if (!s_byte_not01) fmt = 1;
            else fmt = 2;
            g_flag_fmt = fmt;
        }
    } else {
        int tid = (blockIdx.x - 1) * blockDim.x + threadIdx.x;
        int stride = (gridDim.x - 1) * blockDim.x;
        int* cnt = (int*)g_cnt;
        for (int i = tid; i < 2 * Nn; i += stride) cnt[i] = 0;
    }
}

// ---------------- projection: fs = x W_src^T + b_src ; fd likewise ----------------
#define BR 16
__global__ void k_proj(const float* __restrict__ x,
                       const float* __restrict__ Ws, const float* __restrict__ bs,
                       const float* __restrict__ Wd, const float* __restrict__ bd) {
    __shared__ float xs[BR][INd];
    const int row0 = blockIdx.x * BR;
    for (int i = threadIdx.x; i < BR * INd; i += blockDim.x) {
        int r = i / INd, c = i % INd;
        xs[r][c] = x[(row0 + r) * INd + c];
    }
    __syncthreads();
    const int col = threadIdx.x;
    float accS[BR], accD[BR];
#pragma unroll
    for (int r = 0; r < BR; r++) { accS[r] = 0.f; accD[r] = 0.f; }
    const float* wsr = Ws + col * INd;
    const float* wdr = Wd + col * INd;
    for (int k = 0; k < INd; k++) {
        float ws = __ldg(wsr + k);
        float wd = __ldg(wdr + k);
#pragma unroll
        for (int r = 0; r < BR; r++) {
            float xv = xs[r][k];
            accS[r] += xv * ws;
            accD[r] += xv * wd;
        }
    }
    float bsv = bs[col], bdv = bd[col];
#pragma unroll
    for (int r = 0; r < BR; r++) {
        g_fs[(row0 + r) * INd + col] = accS[r] + bsv;
        g_fd[(row0 + r) * INd + col] = accD[r] + bdv;
    }
}

// ---------------- CSR build: histogram -> scan -> fill (both graphs fused) ----------------
__global__ void k_hist(const int* __restrict__ dst_p, const int* __restrict__ dst_s, int et) {
    const int g = blockIdx.x >= et;
    const int e = (blockIdx.x - g * et) * blockDim.x + threadIdx.x;
    if (e < Ee) atomicAdd(&g_cnt[g][(g ? dst_s : dst_p)[e]], 1);
}

__global__ void k_scan() {  // grid = 2 (one block per graph), 1024 threads
    const int g = blockIdx.x;
    const int t = threadIdx.x;
    const int lane = t & 31, w = t >> 5;
    __shared__ int wsum[32];
    __shared__ int s_carry;
    if (t == 0) { g_off[g][0] = 0; s_carry = 0; }
    __syncthreads();
    for (int base = 0; base < Nn; base += 1024) {
        int i = base + t;
        int c0 = (i < Nn) ? g_cnt[g][i] : 0;
        int v = c0;
#pragma unroll
        for (int o = 1; o < 32; o <<= 1) {
            int u = __shfl_up_sync(0xFFFFFFFFu, v, o);
            if (lane >= o) v += u;
        }
        if (lane == 31) wsum[w] = v;
        __syncthreads();
        if (w == 0) {
            int sv = wsum[lane];
#pragma unroll
            for (int o = 1; o < 32; o <<= 1) {
                int u = __shfl_up_sync(0xFFFFFFFFu, sv, o);
                if (lane >= o) sv += u;
            }
            wsum[lane] = sv;
        }
        __syncthreads();
        int add = (w > 0) ? wsum[w - 1] : 0;
        int incl = v + add + s_carry;
        if (i < Nn) {
            g_off[g][i + 1] = incl;
            g_cur[g][i] = incl - c0;
        }
        __syncthreads();
        if (t == 1023) s_carry = incl;
        __syncthreads();
    }
}

__global__ void k_fill(const int* __restrict__ src_p, const int* __restrict__ dst_p,
                       const int* __restrict__ src_s, const int* __restrict__ dst_s, int et) {
    const int g = blockIdx.x >= et;
    const int e = (blockIdx.x - g * et) * blockDim.x + threadIdx.x;
    if (e >= Ee) return;
    const int d = (g ? dst_s : dst_p)[e];
    const int s = (g ? src_s : src_p)[e];
    int pos = atomicAdd(&g_cur[g][d], 1);
    g_srcs[g][pos] = s;
}

// ---------------- fused gather: softmax (2-pass) + aggregation + epilogues ----------------
__global__ void __launch_bounds__(256) k_gather(
        const float* __restrict__ x, const float* __restrict__ y,
        const float* __restrict__ attn, const void* __restrict__ flag,
        float* __restrict__ out) {
    const int warp = threadIdx.x >> 5;
    const int lane = threadIdx.x & 31;
    const int n = blockIdx.x * (blockDim.x >> 5) + warp;
    if (n >= Nn) return;

    __shared__ float4 s_ex[8][MAXD];    // 16 KB: per-edge exp(logit) by head
    __shared__ int    s_src[8][MAXD];   // 4 KB: per-edge src id

    const float4* __restrict__ y4 = (const float4*)y;
    const float4* __restrict__ fs4p = (const float4*)g_fs;

    const float4 fd4 = __ldg(((const float4*)g_fd) + n * 32 + lane);   // once per node
    const float4 at  = __ldg(((const float4*)attn) + lane);

    float4 acc = __ldg(((const float4*)x) + n * 32 + lane);
    acc.x *= 2.f; acc.y *= 2.f; acc.z *= 2.f; acc.w *= 2.f;
    float4 yh[4];
#pragma unroll
    for (int i = 0; i < 4; i++) yh[i] = make_float4(0.f, 0.f, 0.f, 0.f);

#pragma unroll
    for (int g = 0; g < 2; g++) {
        const int beg = g_off[g][n];
        const int end = g_off[g][n + 1];
        const int* __restrict__ ps = g_srcs[g];

        // ---- pass 1: logits -> exp, denominator in registers, stash ex/src in smem
        float dsum = 0.f;   // denominator for head (lane>>3)
        for (int k = beg; k < end; k++) {
            const int idx = k - beg;
            const int s = __ldg(ps + k);
            const float4 f = __ldg(fs4p + s * 32 + lane);
            float v, p;
            v = f.x + fd4.x; v = v > 0.f ? v : SLOPE * v; p  = v * at.x;
            v = f.y + fd4.y; v = v > 0.f ? v : SLOPE * v; p += v * at.y;
            v = f.z + fd4.z; v = v > 0.f ? v : SLOPE * v; p += v * at.z;
            v = f.w + fd4.w; v = v > 0.f ? v : SLOPE * v; p += v * at.w;
            p += __shfl_xor_sync(0xFFFFFFFFu, p, 4);
            p += __shfl_xor_sync(0xFFFFFFFFu, p, 2);
            p += __shfl_xor_sync(0xFFFFFFFFu, p, 1);
            const float ex = expf(p);      // uniform within each 8-lane head group
            dsum += ex;
            const float e0 = __shfl_sync(0xFFFFFFFFu, ex, 0);
            const float e1 = __shfl_sync(0xFFFFFFFFu, ex, 8);
            const float e2 = __shfl_sync(0xFFFFFFFFu, ex, 16);
            const float e3 = __shfl_sync(0xFFFFFFFFu, ex, 24);
            if (idx < MAXD && lane == 0) {
                s_src[warp][idx] = s;
                s_ex[warp][idx] = make_float4(e0, e1, e2, e3);
            }
        }
        __syncwarp();
        const float d0 = __shfl_sync(0xFFFFFFFFu, dsum, 0);
        const float d1 = __shfl_sync(0xFFFFFFFFu, dsum, 8);
        const float d2 = __shfl_sync(0xFFFFFFFFu, dsum, 16);
        const float d3 = __shfl_sync(0xFFFFFFFFu, dsum, 24);
        float4 rs;
        rs.x = 1.f / d0; rs.y = 1.f / d1; rs.z = 1.f / d2; rs.w = 1.f / d3;

        // ---- pass 2: normalize, aggregate fs (L1/L2-hot) and y
        for (int k = beg; k < end; k++) {
            const int idx = k - beg;
            int s; float4 e4;
            if (idx < MAXD) {
                s = s_src[warp][idx];
                e4 = s_ex[warp][idx];
            } else {            // never expected; correctness fallback
                s = __ldg(ps + k);
                const float4 f = __ldg(fs4p + s * 32 + lane);
                float v, p;
                v = f.x + fd4.x; v = v > 0.f ? v : SLOPE * v; p  = v * at.x;
                v = f.y + fd4.y; v = v > 0.f ? v : SLOPE * v; p += v * at.y;
                v = f.z + fd4.z; v = v > 0.f ? v : SLOPE * v; p += v * at.z;
                v = f.w + fd4.w; v = v > 0.f ? v : SLOPE * v; p += v * at.w;
                p += __shfl_xor_sync(0xFFFFFFFFu, p, 4);
                p += __shfl_xor_sync(0xFFFFFFFFu, p, 2);
                p += __shfl_xor_sync(0xFFFFFFFFu, p, 1);
                const float ex = expf(p);
                e4.x = __shfl_sync(0xFFFFFFFFu, ex, 0);
                e4.y = __shfl_sync(0xFFFFFFFFu, ex, 8);
                e4.z = __shfl_sync(0xFFFFFFFFu, ex, 16);
                e4.w = __shfl_sync(0xFFFFFFFFu, ex, 24);
            }
            float4 a4;
            a4.x = e4.x * rs.x; a4.y = e4.y * rs.y; a4.z = e4.z * rs.z; a4.w = e4.w * rs.w;
            const float am = 0.25f * (a4.x + a4.y + a4.z + a4.w);
            const float ah = (lane < 8) ? a4.x : (lane < 16) ? a4.y : (lane < 24) ? a4.z : a4.w;
            const float4 fv = __ldg(fs4p + s * 32 + lane);
            acc.x += fv.x * ah; acc.y += fv.y * ah;
            acc.z += fv.z * ah; acc.w += fv.w * ah;
            const float4* py = y4 + (size_t)s * 128;
#pragma unroll
            for (int i = 0; i < 4; i++) {
                const float4 v = __ldg(py + i * 32 + lane);
                yh[i].x += v.x * am; yh[i].y += v.y * am;
                yh[i].z += v.z * am; yh[i].w += v.w * am;
            }
        }
        __syncwarp();
    }

    // ---- epilogue h: mean over heads + elu; heads of float f live in lanes {f/4, +8, +16, +24}
#pragma unroll
    for (int o = 8; o <= 16; o <<= 1) {
        acc.x += __shfl_xor_sync(0xFFFFFFFFu, acc.x, o);
        acc.y += __shfl_xor_sync(0xFFFFFFFFu, acc.y, o);
        acc.z += __shfl_xor_sync(0xFFFFFFFFu, acc.z, o);
        acc.w += __shfl_xor_sync(0xFFFFFFFFu, acc.w, o);
    }
    if (lane < 8) {
        float4 r;
        r.x = acc.x * 0.25f; r.y = acc.y * 0.25f; r.z = acc.z * 0.25f; r.w = acc.w * 0.25f;
        r.x = r.x > 0.f ? r.x : expm1f(r.x);
        r.y = r.y > 0.f ? r.y : expm1f(r.y);
        r.z = r.z > 0.f ? r.z : expm1f(r.z);
        r.w = r.w > 0.f ? r.w : expm1f(r.w);
        ((float4*)out)[n * 8 + lane] = r;
    }

    // ---- epilogue y: L2 normalize or passthrough per flag
    float ssq = 0.f;
#pragma unroll
    for (int i = 0; i < 4; i++)
        ssq += yh[i].x * yh[i].x + yh[i].y * yh[i].y + yh[i].z * yh[i].z + yh[i].w * yh[i].w;
#pragma unroll
    for (int o = 16; o; o >>= 1) ssq += __shfl_xor_sync(0xFFFFFFFFu, ssq, o);
    const float inv = 1.f / fmaxf(sqrtf(ssq), 1e-12f);

    bool f;
    const int fmt = g_flag_fmt;
    if (fmt == 0)      f = ((const int*)flag)[n] != 0;
    else if (fmt == 1) f = ((const unsigned char*)flag)[n] != 0;
    else               f = ((const float*)flag)[n] != 0.f;

    float4* po = (float4*)(out + (size_t)Nn * Ff) + (size_t)n * 128;
    if (f) {
        const float4* py = y4 + (size_t)n * 128;
#pragma unroll
        for (int i = 0; i < 4; i++) po[i * 32 + lane] = __ldg(py + i * 32 + lane);
    } else {
#pragma unroll
        for (int i = 0; i < 4; i++) {
            float4 w = yh[i];
            w.x *= inv; w.y *= inv; w.z *= inv; w.w *= inv;
            po[i * 32 + lane] = w;
        }
    }
}

// ---------------- launch ----------------
extern "C" void kernel_launch(void* const* d_in, const int* in_sizes, int n_in,
                              void* d_out, int out_size) {
    const float* x     = (const float*)d_in[0];
    const float* y     = (const float*)d_in[1];
    const float* Ws    = (const float*)d_in[2];
    const float* bs    = (const float*)d_in[3];
    const float* Wd    = (const float*)d_in[4];
    const float* bd    = (const float*)d_in[5];
    const float* attn  = (const float*)d_in[6];
    const int*   src_p = (const int*)d_in[7];
    const int*   dst_p = (const int*)d_in[8];
    const int*   src_s = (const int*)d_in[9];
    const int*   dst_s = (const int*)d_in[10];
    const void*  dflag = d_in[11];
    float* out = (float*)d_out;

    const int et = (Ee + 255) / 256;   // thread-per-edge blocks (per graph)

    k_init<<<129, 256>>>((const unsigned*)dflag);
    k_proj<<<Nn / BR, 128>>>(x, Ws, bs, Wd, bd);

    k_hist<<<2 * et, 256>>>(dst_p, dst_s, et);
    k_scan<<<2, 1024>>>();
    k_fill<<<2 * et, 256>>>(src_p, dst_p, src_s, dst_s, et);

    k_gather<<<(Nn + 7) / 8, 256>>>(x, y, attn, dflag, out);
}